// round 2
// baseline (speedup 1.0000x reference)
#include <cuda_runtime.h>
#include <cstdint>

// Problem constants (fixed shapes for this problem instance)
#define ITEMS_TOTAL 50000
#define DIM         64
#define BATCH       16
#define NPG         50           // n_per_graph
#define VEC4_PER_ROW (DIM / 4)   // 16 float4 per row

// Kernel 1: broadcast emb_table -> all BATCH output slices.
// One thread per float4 of emb_table; writes it to 16 batch offsets.
// DRAM traffic: 12.8 MB read + 204.8 MB write.
__global__ void __launch_bounds__(256)
broadcast_kernel(const float4* __restrict__ emb4, float4* __restrict__ out4) {
    const long long n4 = (long long)ITEMS_TOTAL * VEC4_PER_ROW;  // 800,000
    long long t = (long long)blockIdx.x * blockDim.x + threadIdx.x;
    if (t >= n4) return;
    float4 v = emb4[t];
#pragma unroll
    for (int b = 0; b < BATCH; b++) {
        out4[(long long)b * n4 + t] = v;
    }
}

// Kernel 2: scatter the 800 updated rows.
// out[b, idx, :] = (1 - alpha[idx]) * emb[idx, :] + alpha[idx] * feat[b, j, :]
// Only the LAST occurrence of a duplicate idx within a graph writes.
// nodes dtype (int32 vs int64) is detected on-device: if the buffer is
// little-endian int64 with values < 50000, every high word is 0.
__global__ void __launch_bounds__(128)
scatter_kernel(const void*  __restrict__ nodes_raw,
               const float* __restrict__ feat,   // (BATCH*NPG, DIM)
               const float* __restrict__ emb,    // (ITEMS_TOTAL, DIM)
               const float* __restrict__ alpha,  // (ITEMS_TOTAL, 1)
               float*       __restrict__ out) {  // (BATCH, ITEMS_TOTAL, DIM)
    // --- dtype detection (3200 bytes, in-bounds for both layouts) ---
    __shared__ int s_not64;
    if (threadIdx.x == 0) s_not64 = 0;
    __syncthreads();
    const int* a32 = (const int*)nodes_raw;
    for (int k = threadIdx.x; k < 400; k += blockDim.x) {
        if (a32[2 * k + 1] != 0) s_not64 = 1;   // benign race: all writers store 1
    }
    __syncthreads();
    const bool is64 = (s_not64 == 0);
    const long long* a64 = (const long long*)nodes_raw;

    int t = blockIdx.x * blockDim.x + threadIdx.x;
    const int total = BATCH * NPG * VEC4_PER_ROW;  // 12,800
    if (t >= total) return;
    int j    = t >> 4;          // global node position 0..799
    int lane = t & 15;          // float4 lane within row
    int b  = j / NPG;
    int jl = j % NPG;
    long long idx = is64 ? a64[j] : (long long)a32[j];
    // last-occurrence check: skip if a later position in this graph has same idx
    for (int jj = jl + 1; jj < NPG; jj++) {
        int p = b * NPG + jj;
        long long other = is64 ? a64[p] : (long long)a32[p];
        if (other == idx) return;
    }
    float a = alpha[idx];
    const float4* e4 = reinterpret_cast<const float4*>(emb  + idx * DIM);
    const float4* f4 = reinterpret_cast<const float4*>(feat + (long long)j * DIM);
    float4 ev = e4[lane];
    float4 fv = f4[lane];
    float4 r;
    r.x = fmaf(a, fv.x, (1.0f - a) * ev.x);
    r.y = fmaf(a, fv.y, (1.0f - a) * ev.y);
    r.z = fmaf(a, fv.z, (1.0f - a) * ev.z);
    r.w = fmaf(a, fv.w, (1.0f - a) * ev.w);
    long long row_off = ((long long)b * ITEMS_TOTAL + idx) * DIM;
    reinterpret_cast<float4*>(out + row_off)[lane] = r;
}

extern "C" void kernel_launch(void* const* d_in, const int* in_sizes, int n_in,
                              void* d_out, int out_size) {
    // Inputs (metadata order):
    // 0: nodes        int32/int64 (BATCH*NPG,)
    // 1: nodes_output float32     (BATCH*NPG, DIM)
    // 2: emb_table    float32     (ITEMS_TOTAL, DIM)
    // 3: alpha        float32     (ITEMS_TOTAL, 1)
    // 4: n_per_graph  scalar (unused; fixed at compile time)
    const void*  nodes = d_in[0];
    const float* feat  = (const float*)d_in[1];
    const float* emb   = (const float*)d_in[2];
    const float* alpha = (const float*)d_in[3];
    float*       out   = (float*)d_out;

    // Broadcast: 800,000 float4 threads
    {
        const long long n4 = (long long)ITEMS_TOTAL * VEC4_PER_ROW;
        int threads = 256;
        int blocks  = (int)((n4 + threads - 1) / threads);
        broadcast_kernel<<<blocks, threads>>>(
            reinterpret_cast<const float4*>(emb),
            reinterpret_cast<float4*>(out));
    }
    // Scatter: 12,800 threads (after broadcast on same stream)
    {
        int total   = BATCH * NPG * VEC4_PER_ROW;
        int threads = 128;
        int blocks  = (total + threads - 1) / threads;
        scatter_kernel<<<blocks, threads>>>(nodes, feat, emb, alpha, out);
    }
}